// round 4
// baseline (speedup 1.0000x reference)
#include <cuda_runtime.h>
#include <cuda_bf16.h>
#include <math.h>
#include <stdint.h>

#define BATCH 2
#define SEQ   2048
#define DM    1024
#define NH    16
#define HD    64
#define MR    (BATCH*SEQ)   // 4096

// ---------------------------------------------------------------------------
// Scratch (allocation-free rule: device globals)
// ---------------------------------------------------------------------------
__device__ __nv_bfloat16 g_Xhi[(size_t)MR * DM];
__device__ __nv_bfloat16 g_Xlo[(size_t)MR * DM];
// WT rows: 0-1023 WqT, 1024-2047 WkT, 2048-3071 WvT, 3072-4095 WoT  ([n][k])
__device__ __nv_bfloat16 g_WThi[(size_t)4096 * DM];
__device__ __nv_bfloat16 g_WTlo[(size_t)4096 * DM];
__device__ float         g_bias[4096];          // bq|bk|bv|bo
__device__ __nv_bfloat16 g_QKVhi[(size_t)MR * 3072];
__device__ __nv_bfloat16 g_QKVlo[(size_t)MR * 3072];
__device__ __nv_bfloat16 g_AOhi[(size_t)MR * DM];
__device__ __nv_bfloat16 g_AOlo[(size_t)MR * DM];

// ---------------------------------------------------------------------------
// PTX helpers (all sm_80-era: compile at compute_103)
// ---------------------------------------------------------------------------
__device__ __forceinline__ uint32_t smem_u32(const void* p) {
    uint32_t a;
    asm("{ .reg .u64 t; cvta.to.shared.u64 t, %1; cvt.u32.u64 %0, t; }"
        : "=r"(a) : "l"(p));
    return a;
}

__device__ __forceinline__ void mma_bf16(float* d, const uint32_t* a, const uint32_t* b) {
    asm volatile(
        "mma.sync.aligned.m16n8k16.row.col.f32.bf16.bf16.f32 "
        "{%0,%1,%2,%3}, {%4,%5,%6,%7}, {%8,%9}, {%0,%1,%2,%3};"
        : "+f"(d[0]), "+f"(d[1]), "+f"(d[2]), "+f"(d[3])
        : "r"(a[0]), "r"(a[1]), "r"(a[2]), "r"(a[3]), "r"(b[0]), "r"(b[1]));
}

__device__ __forceinline__ void ldm_x4(uint32_t* r, uint32_t addr) {
    asm volatile("ldmatrix.sync.aligned.m8n8.x4.shared.b16 {%0,%1,%2,%3}, [%4];"
                 : "=r"(r[0]), "=r"(r[1]), "=r"(r[2]), "=r"(r[3]) : "r"(addr));
}
__device__ __forceinline__ void ldm_x2t(uint32_t* r, uint32_t addr) {
    asm volatile("ldmatrix.sync.aligned.m8n8.x2.trans.shared.b16 {%0,%1}, [%2];"
                 : "=r"(r[0]), "=r"(r[1]) : "r"(addr));
}

#define CP16(sm, g) \
    asm volatile("cp.async.cg.shared.global [%0], [%1], 16;" :: "r"(sm), "l"(g))
#define CP_COMMIT asm volatile("cp.async.commit_group;")
#define CP_WAIT0  asm volatile("cp.async.wait_group 0;" ::: "memory")
#define CP_WAIT1  asm volatile("cp.async.wait_group 1;" ::: "memory")

__device__ __forceinline__ void split2(float a, float b, uint32_t& hi, uint32_t& lo) {
    __nv_bfloat162 H = __floats2bfloat162_rn(a, b);
    float ra = a - __bfloat162float(H.x);
    float rb = b - __bfloat162float(H.y);
    __nv_bfloat162 L = __floats2bfloat162_rn(ra, rb);
    hi = *(uint32_t*)&H;
    lo = *(uint32_t*)&L;
}

__device__ __forceinline__ void store_split(__nv_bfloat16* Chi, __nv_bfloat16* Clo,
                                            size_t idx, float v0, float v1) {
    uint32_t h, l;
    split2(v0, v1, h, l);
    *(uint32_t*)(Chi + idx) = h;
    *(uint32_t*)(Clo + idx) = l;
}

// ---------------------------------------------------------------------------
// Conversion kernels
// ---------------------------------------------------------------------------
__global__ void split_f32(const float* __restrict__ src,
                          __nv_bfloat16* __restrict__ hi,
                          __nv_bfloat16* __restrict__ lo, int n4)
{
    int i = blockIdx.x * blockDim.x + threadIdx.x;
    if (i >= n4) return;
    float4 v = ((const float4*)src)[i];
    store_split(hi, lo, 4 * (size_t)i,     v.x, v.y);
    store_split(hi, lo, 4 * (size_t)i + 2, v.z, v.w);
}

// W [K][N] fp32 -> WT hi/lo [N][K] bf16 (transpose + split)
__global__ void split_wT(const float* __restrict__ W,
                         __nv_bfloat16* __restrict__ Thi,
                         __nv_bfloat16* __restrict__ Tlo)
{
    __shared__ float t[32][33];
    const int k0 = blockIdx.y * 32, n0 = blockIdx.x * 32;
    const int tx = threadIdx.x, ty = threadIdx.y;
    #pragma unroll
    for (int i = ty; i < 32; i += 8)
        t[i][tx] = W[(size_t)(k0 + i) * DM + n0 + tx];
    __syncthreads();
    #pragma unroll
    for (int i = ty; i < 32; i += 8) {
        float v = t[tx][i];
        __nv_bfloat16 h = __float2bfloat16_rn(v);
        Thi[(size_t)(n0 + i) * DM + k0 + tx] = h;
        Tlo[(size_t)(n0 + i) * DM + k0 + tx] =
            __float2bfloat16_rn(v - __bfloat162float(h));
    }
}

__global__ void concat_bias(const float* bq, const float* bk, const float* bv,
                            const float* bo, float* dst)
{
    int i = blockIdx.x * blockDim.x + threadIdx.x;
    if (i >= 4096) return;
    float v;
    if      (i < 1024) v = bq[i];
    else if (i < 2048) v = bk[i - 1024];
    else if (i < 3072) v = bv[i - 2048];
    else               v = bo[i - 3072];
    dst[i] = v;
}

// ---------------------------------------------------------------------------
// Split-bf16 x3 GEMM on mma.sync:  C[M,N] = A[M,1024] @ B^T + bias
// CTA 128x128, BK=32, 8 warps (4x2, warp tile 32x64), cp.async double buffer
// ---------------------------------------------------------------------------
#define TSZ 10240u   // one 128x40-b16 tile in bytes
#define GEMM_SMEM (8u * TSZ)   // 81920

template<bool TOF32>
__global__ __launch_bounds__(256) void gemm_mma(
    const __nv_bfloat16* __restrict__ Ahi, const __nv_bfloat16* __restrict__ Alo,
    const __nv_bfloat16* __restrict__ Bhi, const __nv_bfloat16* __restrict__ Blo,
    const float* __restrict__ bias, float* __restrict__ Cf,
    __nv_bfloat16* __restrict__ Chi, __nv_bfloat16* __restrict__ Clo,
    int ldc, int qscale)
{
    extern __shared__ char smc[];
    const uint32_t sb = smem_u32(smc);
    const int tid = threadIdx.x, lane = tid & 31, wid = tid >> 5;
    const int wm = wid >> 1, wn = wid & 1;
    const int g = lane >> 2, tg = lane & 3;
    const int brow = blockIdx.y * 128, bcol = blockIdx.x * 128;
    const int lr = tid >> 2, lq = tid & 3;

    auto issue = [&](int buf, int kc) {
        #pragma unroll
        for (int rep = 0; rep < 2; rep++) {
            int row = lr + rep * 64;
            size_t ga = (size_t)(brow + row) * DM + kc + lq * 8;
            size_t gb = (size_t)(bcol + row) * DM + kc + lq * 8;
            uint32_t off = sb + (uint32_t)buf * 4u * TSZ
                         + (uint32_t)(row * 40 + lq * 8) * 2u;
            CP16(off,            Ahi + ga);
            CP16(off + TSZ,      Alo + ga);
            CP16(off + 2u * TSZ, Bhi + gb);
            CP16(off + 3u * TSZ, Blo + gb);
        }
        CP_COMMIT;
    };

    float acc[2][8][4];
    #pragma unroll
    for (int a = 0; a < 2; a++)
        #pragma unroll
        for (int b = 0; b < 8; b++)
            #pragma unroll
            for (int c = 0; c < 4; c++) acc[a][b][c] = 0.f;

    issue(0, 0);

    for (int c = 0; c < 32; c++) {
        CP_WAIT0;
        __syncthreads();
        if (c < 31) issue((c + 1) & 1, (c + 1) * 32);
        const uint32_t tb = sb + (uint32_t)(c & 1) * 4u * TSZ;

        #pragma unroll
        for (int kk = 0; kk < 32; kk += 16) {
            uint32_t ah[2][4], al[2][4], bh[8][2], bl[8][2];
            #pragma unroll
            for (int fm = 0; fm < 2; fm++) {
                uint32_t ra = (uint32_t)((wm * 32 + fm * 16 + (lane & 7)
                              + 8 * ((lane >> 3) & 1)) * 40
                              + kk + 8 * (lane >> 4)) * 2u;
                ldm_x4(ah[fm], tb + ra);
                ldm_x4(al[fm], tb + TSZ + ra);
            }
            #pragma unroll
            for (int i = 0; i < 4; i++) {
                uint32_t rb = (uint32_t)((wn * 64 + i * 16 + (lane & 7)
                              + 8 * (lane >> 4)) * 40
                              + kk + 8 * ((lane >> 3) & 1)) * 2u;
                uint32_t t4[4];
                ldm_x4(t4, tb + 2u * TSZ + rb);
                bh[2*i][0] = t4[0]; bh[2*i][1] = t4[1];
                bh[2*i+1][0] = t4[2]; bh[2*i+1][1] = t4[3];
                ldm_x4(t4, tb + 3u * TSZ + rb);
                bl[2*i][0] = t4[0]; bl[2*i][1] = t4[1];
                bl[2*i+1][0] = t4[2]; bl[2*i+1][1] = t4[3];
            }
            #pragma unroll
            for (int fm = 0; fm < 2; fm++)
                #pragma unroll
                for (int fn = 0; fn < 8; fn++) {
                    mma_bf16(acc[fm][fn], ah[fm], bh[fn]);
                    mma_bf16(acc[fm][fn], ah[fm], bl[fn]);
                    mma_bf16(acc[fm][fn], al[fm], bh[fn]);
                }
        }
    }

    #pragma unroll
    for (int fm = 0; fm < 2; fm++) {
        int row = brow + wm * 32 + fm * 16 + g;
        #pragma unroll
        for (int fn = 0; fn < 8; fn++) {
            int col = bcol + wn * 64 + fn * 8 + 2 * tg;
            float sc = (qscale && col < 1024) ? 0.125f : 1.0f;
            float b0 = bias[col], b1 = bias[col + 1];
            float v0 = (acc[fm][fn][0] + b0) * sc;
            float v1 = (acc[fm][fn][1] + b1) * sc;
            float v2 = (acc[fm][fn][2] + b0) * sc;
            float v3 = (acc[fm][fn][3] + b1) * sc;
            if (TOF32) {
                *(float2*)&Cf[(size_t)row * ldc + col]       = make_float2(v0, v1);
                *(float2*)&Cf[(size_t)(row + 8) * ldc + col] = make_float2(v2, v3);
            } else {
                store_split(Chi, Clo, (size_t)row * ldc + col,       v0, v1);
                store_split(Chi, Clo, (size_t)(row + 8) * ldc + col, v2, v3);
            }
        }
    }
}

// ---------------------------------------------------------------------------
// Flash attention on mma.sync, split-bf16 x3, Br=128 / Bc=64.
// 256 threads (8 warps x 16 q-rows). cp.async double-buffered K/V.
// Descending-qb launch order; per-warp skip of fully masked tiles.
// Q pre-scaled by 1/8 at the QKV GEMM epilogue.
// ---------------------------------------------------------------------------
#define AST 72        // b16 row stride (144B: 16B-aligned, ldmatrix conflict-free)
#define QH_O 0u
#define QL_O 18432u
#define KVB_O 36864u
#define KVB_STRIDE 36864u
#define KH_O 0u
#define KL_O 9216u
#define VH_O 18432u
#define VL_O 27648u
#define ATTN_SMEM 110592

__global__ __launch_bounds__(256) void attn_mma()
{
    extern __shared__ char smc[];
    const uint32_t sb = smem_u32(smc);
    const int tid = threadIdx.x, lane = tid & 31, w = tid >> 5;
    const int g = lane >> 2, tg = lane & 3;
    const int qb = (int)gridDim.x - 1 - (int)blockIdx.x;   // heavy blocks first
    const int h = blockIdx.y, b = blockIdx.z;
    const int qbase = qb * 128;
    const size_t rowb = (size_t)b * SEQ;
    const int hoff = h * HD;

    auto issue_kv = [&](int kb, int buf) {
        const int kbase = kb * 64;
        const uint32_t bb = sb + KVB_O + (uint32_t)buf * KVB_STRIDE;
        #pragma unroll
        for (int i = 0; i < 8; i++) {
            int slot = tid + 256 * i;            // 0..2047
            int r = (slot >> 3) & 63, q8 = slot & 7;
            int arr = slot >> 9;                 // 0 KH, 1 KL, 2 VH, 3 VL
            size_t go = (rowb + kbase + r) * 3072 + hoff
                      + ((arr >> 1) ? 2048 : 1024) + q8 * 8;
            const __nv_bfloat16* src = (arr & 1) ? g_QKVlo : g_QKVhi;
            uint32_t so = bb + (uint32_t)arr * 9216u
                        + (uint32_t)(r * AST + q8 * 8) * 2u;
            CP16(so, src + go);
        }
    };

    // Q (hi/lo) async load: 2 arrays x 128 rows x 8 chunks
    #pragma unroll
    for (int i = 0; i < 8; i++) {
        int slot = tid + 256 * i;                // 0..2047
        int r = (slot >> 3) & 127, q8 = slot & 7, arr = slot >> 10;
        size_t go = (rowb + qbase + r) * 3072 + hoff + q8 * 8;
        uint32_t so = sb + (arr ? QL_O : QH_O) + (uint32_t)(r * AST + q8 * 8) * 2u;
        CP16(so, (arr ? g_QKVlo : g_QKVhi) + go);
    }
    issue_kv(0, 0);
    CP_COMMIT;     // group 0 = Q + KV(0)

    float o[8][4];
    #pragma unroll
    for (int fn = 0; fn < 8; fn++)
        #pragma unroll
        for (int c = 0; c < 4; c++) o[fn][c] = 0.f;
    float m0 = -1e30f, m1 = -1e30f, l0 = 0.f, l1 = 0.f;

    const int nk = 2 * qb + 2;
    for (int kb = 0; kb < nk; kb++) {
        __syncthreads();                         // all warps done with buf[(kb+1)&1]
        if (kb + 1 < nk) {
            issue_kv(kb + 1, (kb + 1) & 1);
            CP_COMMIT;
            CP_WAIT1;                            // tile kb (and Q) resident
        } else {
            CP_WAIT0;
        }
        __syncthreads();

        const uint32_t tb = sb + KVB_O + (uint32_t)(kb & 1) * KVB_STRIDE;
        const int kbase = kb * 64;
        const int wrow = qbase + w * 16;         // warp's min q-row
        if (kbase > wrow + 15) continue;         // fully masked tile for this warp

        // ---- S = Q @ K^T ----
        float s[8][4];
        #pragma unroll
        for (int fn = 0; fn < 8; fn++)
            #pragma unroll
            for (int c = 0; c < 4; c++) s[fn][c] = 0.f;

        #pragma unroll
        for (int kk = 0; kk < 64; kk += 16) {
            uint32_t qh[4], ql[4];
            uint32_t ra = sb + (uint32_t)((w * 16 + (lane & 7)
                          + 8 * ((lane >> 3) & 1)) * AST
                          + kk + 8 * (lane >> 4)) * 2u;
            ldm_x4(qh, ra + QH_O);
            ldm_x4(ql, ra + QL_O);
            #pragma unroll
            for (int i = 0; i < 4; i++) {
                uint32_t rb = tb + (uint32_t)((i * 16 + (lane & 7)
                              + 8 * (lane >> 4)) * AST
                              + kk + 8 * ((lane >> 3) & 1)) * 2u;
                uint32_t th[4], tl[4];
                ldm_x4(th, rb + KH_O);
                ldm_x4(tl, rb + KL_O);
                mma_bf16(s[2*i],     qh, th);
                mma_bf16(s[2*i],     qh, tl);
                mma_bf16(s[2*i],     ql, th);
                mma_bf16(s[2*i+1],   qh, th + 2);
                mma_bf16(s[2*i+1],   qh, tl + 2);
                mma_bf16(s[2*i+1],   ql, th + 2);
            }
        }

        // ---- causal mask (diagonal region only) ----
        if (kbase + 63 > wrow) {
            const int lr0 = wrow + g, lr1 = lr0 + 8;   // global q-rows
            #pragma unroll
            for (int fn = 0; fn < 8; fn++) {
                int c0 = kbase + fn * 8 + 2 * tg;
                if (c0     > lr0) s[fn][0] = -1e30f;
                if (c0 + 1 > lr0) s[fn][1] = -1e30f;
                if (c0     > lr1) s[fn][2] = -1e30f;
                if (c0 + 1 > lr1) s[fn][3] = -1e30f;
            }
        }

        // ---- online softmax ----
        float rm0 = -1e30f, rm1 = -1e30f;
        #pragma unroll
        for (int fn = 0; fn < 8; fn++) {
            rm0 = fmaxf(rm0, fmaxf(s[fn][0], s[fn][1]));
            rm1 = fmaxf(rm1, fmaxf(s[fn][2], s[fn][3]));
        }
        rm0 = fmaxf(rm0, __shfl_xor_sync(0xffffffffu, rm0, 1));
        rm0 = fmaxf(rm0, __shfl_xor_sync(0xffffffffu, rm0, 2));
        rm1 = fmaxf(rm1, __shfl_xor_sync(0xffffffffu, rm1, 1));
        rm1 = fmaxf(rm1, __shfl_xor_sync(0xffffffffu, rm1, 2));
        const float mn0 = fmaxf(m0, rm0), mn1 = fmaxf(m1, rm1);
        const float c0f = __expf(m0 - mn0), c1f = __expf(m1 - mn1);
        m0 = mn0; m1 = mn1;
        float sum0 = 0.f, sum1 = 0.f;
        #pragma unroll
        for (int fn = 0; fn < 8; fn++) {
            s[fn][0] = __expf(s[fn][0] - mn0); sum0 += s[fn][0];
            s[fn][1] = __expf(s[fn][1] - mn0); sum0 += s[fn][1];
            s[fn][2] = __expf(s[fn][2] - mn1); sum1 += s[fn][2];
            s[fn][3] = __expf(s[fn][3] - mn1); sum1 += s[fn][3];
        }
        sum0 += __shfl_xor_sync(0xffffffffu, sum0, 1);
        sum0 += __shfl_xor_sync(0xffffffffu, sum0, 2);
        sum1 += __shfl_xor_sync(0xffffffffu, sum1, 1);
        sum1 += __shfl_xor_sync(0xffffffffu, sum1, 2);
        l0 = l0 * c0f + sum0;
        l1 = l1 * c1f + sum1;
        #pragma unroll
        for (int fn = 0; fn < 8; fn++) {
            o[fn][0] *= c0f; o[fn][1] *= c0f;
            o[fn][2] *= c1f; o[fn][3] *= c1f;
        }

        // ---- O += P @ V ----
        #pragma unroll
        for (int kk = 0; kk < 64; kk += 16) {
            const int f0 = kk >> 3, f1 = f0 + 1;
            uint32_t ph[4], pl[4];
            split2(s[f0][0], s[f0][1], ph[0], pl[0]);
            split2(s[f0][2], s[f0][3], ph[1], pl[1]);
            split2(s[f1][0], s[f1][1], ph[2], pl[2]);
            split2(s[f1][2], s[f1][3], ph[3], pl[3]);
            uint32_t rv = tb + (uint32_t)((kk + (lane & 15)) * AST) * 2u;
            #pragma unroll
            for (int fn = 0; fn < 8; fn++) {
                uint32_t vh[2], vl[2];
                ldm_x2t(vh, rv + VH_O + (uint32_t)(fn * 16));
                ldm_x2t(vl, rv + VL_O + (uint32_t)(fn * 16));
                mma_bf16(o[fn], ph, vh);
                mma_bf16(o[fn], ph, vl);
                mma_bf16(o[fn], pl, vh);
            }
        }
    }

    // ---- epilogue: normalize, split-store AO ----
    const float i0 = 1.f / l0, i1 = 1.f / l1;
    const size_t r0 = rowb + qbase + w * 16 + g;
    #pragma unroll
    for (int fn = 0; fn < 8; fn++) {
        int col = hoff + fn * 8 + 2 * tg;
        store_split(g_AOhi, g_AOlo, r0 * DM + col,       o[fn][0] * i0, o[fn][1] * i0);
        store_split(g_AOhi, g_AOlo, (r0 + 8) * DM + col, o[fn][2] * i1, o[fn][3] * i1);
    }
}

// ---------------------------------------------------------------------------
// Launch
// ---------------------------------------------------------------------------
extern "C" void kernel_launch(void* const* d_in, const int* in_sizes, int n_in,
                              void* d_out, int out_size)
{
    const float* X  = (const float*)d_in[0];
    const float* Wq = (const float*)d_in[1];
    const float* bq = (const float*)d_in[2];
    const float* Wk = (const float*)d_in[3];
    const float* bk = (const float*)d_in[4];
    const float* Wv = (const float*)d_in[5];
    const float* bv = (const float*)d_in[6];
    const float* Wo = (const float*)d_in[7];
    const float* bo = (const float*)d_in[8];
    float* out = (float*)d_out;

    __nv_bfloat16 *Xhi, *Xlo, *WThi, *WTlo, *QKVhi, *QKVlo, *AOhi, *AOlo;
    float* biasP;
    cudaGetSymbolAddress((void**)&Xhi,   g_Xhi);
    cudaGetSymbolAddress((void**)&Xlo,   g_Xlo);
    cudaGetSymbolAddress((void**)&WThi,  g_WThi);
    cudaGetSymbolAddress((void**)&WTlo,  g_WTlo);
    cudaGetSymbolAddress((void**)&QKVhi, g_QKVhi);
    cudaGetSymbolAddress((void**)&QKVlo, g_QKVlo);
    cudaGetSymbolAddress((void**)&AOhi,  g_AOhi);
    cudaGetSymbolAddress((void**)&AOlo,  g_AOlo);
    cudaGetSymbolAddress((void**)&biasP, g_bias);

    cudaFuncSetAttribute(gemm_mma<false>,
        cudaFuncAttributeMaxDynamicSharedMemorySize, (int)GEMM_SMEM);
    cudaFuncSetAttribute(gemm_mma<true>,
        cudaFuncAttributeMaxDynamicSharedMemorySize, (int)GEMM_SMEM);
    cudaFuncSetAttribute(attn_mma,
        cudaFuncAttributeMaxDynamicSharedMemorySize, (int)ATTN_SMEM);

    const size_t WSZ = (size_t)DM * DM;
    const int n4 = MR * DM / 4;
    dim3 tgrid(DM / 32, DM / 32);
    dim3 tblk(32, 8);

    split_f32<<<(n4 + 255) / 256, 256>>>(X, Xhi, Xlo, n4);
    split_wT<<<tgrid, tblk>>>(Wq, WThi + 0 * WSZ, WTlo + 0 * WSZ);
    split_wT<<<tgrid, tblk>>>(Wk, WThi + 1 * WSZ, WTlo + 1 * WSZ);
    split_wT<<<tgrid, tblk>>>(Wv, WThi + 2 * WSZ, WTlo + 2 * WSZ);
    split_wT<<<tgrid, tblk>>>(Wo, WThi + 3 * WSZ, WTlo + 3 * WSZ);
    concat_bias<<<16, 256>>>(bq, bk, bv, bo, biasP);

    // fused QKV projection (N=3072), Q region scaled by 1/8, split-bf16 out
    gemm_mma<false><<<dim3(24, 32), 256, GEMM_SMEM>>>(
        Xhi, Xlo, WThi, WTlo, biasP, nullptr, QKVhi, QKVlo, 3072, 1);

    // causal attention, Br=128, split-bf16 out
    attn_mma<<<dim3(SEQ / 128, NH, BATCH), 256, ATTN_SMEM>>>();

    // output projection, fp32 out
    gemm_mma<true><<<dim3(8, 32), 256, GEMM_SMEM>>>(
        AOhi, AOlo, WThi + 3 * WSZ, WTlo + 3 * WSZ, biasP + 3072,
        out, nullptr, nullptr, 1024, 0);
}

// round 6
// speedup vs baseline: 1.0442x; 1.0442x over previous
#include <cuda_runtime.h>
#include <cuda_bf16.h>
#include <math.h>
#include <stdint.h>

#define BATCH 2
#define SEQ   2048
#define DM    1024
#define NH    16
#define HD    64
#define MR    (BATCH*SEQ)   // 4096

// Q pre-scale: log2(e) / sqrt(64)  -> softmax works in exp2 domain
#define QSCALE 0.1803368801111244f

// ---------------------------------------------------------------------------
// Scratch (allocation-free rule: device globals)
// ---------------------------------------------------------------------------
__device__ __nv_bfloat16 g_Xhi[(size_t)MR * DM];
__device__ __nv_bfloat16 g_Xlo[(size_t)MR * DM];
// WT rows: 0-1023 WqT, 1024-2047 WkT, 2048-3071 WvT, 3072-4095 WoT  ([n][k])
__device__ __nv_bfloat16 g_WThi[(size_t)4096 * DM];
__device__ __nv_bfloat16 g_WTlo[(size_t)4096 * DM];
__device__ float         g_bias[4096];          // bq|bk|bv|bo
__device__ __nv_bfloat16 g_QKVhi[(size_t)MR * 3072];
__device__ __nv_bfloat16 g_QKVlo[(size_t)MR * 3072];
__device__ __nv_bfloat16 g_AOhi[(size_t)MR * DM];
__device__ __nv_bfloat16 g_AOlo[(size_t)MR * DM];

// ---------------------------------------------------------------------------
// PTX helpers (all sm_80-era: compile at compute_103)
// ---------------------------------------------------------------------------
__device__ __forceinline__ uint32_t smem_u32(const void* p) {
    uint32_t a;
    asm("{ .reg .u64 t; cvta.to.shared.u64 t, %1; cvt.u32.u64 %0, t; }"
        : "=r"(a) : "l"(p));
    return a;
}

__device__ __forceinline__ float ex2f(float x) {
    float y;
    asm("ex2.approx.f32 %0, %1;" : "=f"(y) : "f"(x));
    return y;
}

__device__ __forceinline__ void mma_bf16(float* d, const uint32_t* a, const uint32_t* b) {
    asm volatile(
        "mma.sync.aligned.m16n8k16.row.col.f32.bf16.bf16.f32 "
        "{%0,%1,%2,%3}, {%4,%5,%6,%7}, {%8,%9}, {%0,%1,%2,%3};"
        : "+f"(d[0]), "+f"(d[1]), "+f"(d[2]), "+f"(d[3])
        : "r"(a[0]), "r"(a[1]), "r"(a[2]), "r"(a[3]), "r"(b[0]), "r"(b[1]));
}

__device__ __forceinline__ void ldm_x4(uint32_t* r, uint32_t addr) {
    asm volatile("ldmatrix.sync.aligned.m8n8.x4.shared.b16 {%0,%1,%2,%3}, [%4];"
                 : "=r"(r[0]), "=r"(r[1]), "=r"(r[2]), "=r"(r[3]) : "r"(addr));
}
__device__ __forceinline__ void ldm_x2t(uint32_t* r, uint32_t addr) {
    asm volatile("ldmatrix.sync.aligned.m8n8.x2.trans.shared.b16 {%0,%1}, [%2];"
                 : "=r"(r[0]), "=r"(r[1]) : "r"(addr));
}

#define CP16(sm, g) \
    asm volatile("cp.async.cg.shared.global [%0], [%1], 16;" :: "r"(sm), "l"(g))
#define CP_COMMIT asm volatile("cp.async.commit_group;")
#define CP_WAIT0  asm volatile("cp.async.wait_group 0;" ::: "memory")

__device__ __forceinline__ void split2(float a, float b, uint32_t& hi, uint32_t& lo) {
    __nv_bfloat162 H = __floats2bfloat162_rn(a, b);
    float ra = a - __bfloat162float(H.x);
    float rb = b - __bfloat162float(H.y);
    __nv_bfloat162 L = __floats2bfloat162_rn(ra, rb);
    hi = *(uint32_t*)&H;
    lo = *(uint32_t*)&L;
}

__device__ __forceinline__ void store_split(__nv_bfloat16* Chi, __nv_bfloat16* Clo,
                                            size_t idx, float v0, float v1) {
    uint32_t h, l;
    split2(v0, v1, h, l);
    *(uint32_t*)(Chi + idx) = h;
    *(uint32_t*)(Clo + idx) = l;
}

// ---------------------------------------------------------------------------
// Conversion kernels
// ---------------------------------------------------------------------------
__global__ void split_f32(const float* __restrict__ src,
                          __nv_bfloat16* __restrict__ hi,
                          __nv_bfloat16* __restrict__ lo, int n4)
{
    int i = blockIdx.x * blockDim.x + threadIdx.x;
    if (i >= n4) return;
    float4 v = ((const float4*)src)[i];
    store_split(hi, lo, 4 * (size_t)i,     v.x, v.y);
    store_split(hi, lo, 4 * (size_t)i + 2, v.z, v.w);
}

// All four W [K][N] fp32 -> WT hi/lo [N][K] bf16 (transpose + split), fused
__global__ void split_wT4(const float* __restrict__ W0, const float* __restrict__ W1,
                          const float* __restrict__ W2, const float* __restrict__ W3,
                          __nv_bfloat16* __restrict__ Thi,
                          __nv_bfloat16* __restrict__ Tlo)
{
    __shared__ float t[32][33];
    const int z = blockIdx.z;
    const float* W = (z == 0) ? W0 : (z == 1) ? W1 : (z == 2) ? W2 : W3;
    __nv_bfloat16* thi = Thi + (size_t)z * DM * DM;
    __nv_bfloat16* tlo = Tlo + (size_t)z * DM * DM;
    const int k0 = blockIdx.y * 32, n0 = blockIdx.x * 32;
    const int tx = threadIdx.x, ty = threadIdx.y;
    #pragma unroll
    for (int i = ty; i < 32; i += 8)
        t[i][tx] = W[(size_t)(k0 + i) * DM + n0 + tx];
    __syncthreads();
    #pragma unroll
    for (int i = ty; i < 32; i += 8) {
        float v = t[tx][i];
        __nv_bfloat16 h = __float2bfloat16_rn(v);
        thi[(size_t)(n0 + i) * DM + k0 + tx] = h;
        tlo[(size_t)(n0 + i) * DM + k0 + tx] =
            __float2bfloat16_rn(v - __bfloat162float(h));
    }
}

__global__ void concat_bias(const float* bq, const float* bk, const float* bv,
                            const float* bo, float* dst)
{
    int i = blockIdx.x * blockDim.x + threadIdx.x;
    if (i >= 4096) return;
    float v;
    if      (i < 1024) v = bq[i];
    else if (i < 2048) v = bk[i - 1024];
    else if (i < 3072) v = bv[i - 2048];
    else               v = bo[i - 3072];
    dst[i] = v;
}

// ---------------------------------------------------------------------------
// Split-bf16 x3 GEMM on mma.sync:  C[M,N] = A[M,1024] @ B^T + bias
// CTA 128x128, BK=32, 8 warps (4x2, warp tile 32x64), cp.async double buffer
// ---------------------------------------------------------------------------
#define TSZ 10240u   // one 128x40-b16 tile in bytes
#define GEMM_SMEM (8u * TSZ)   // 81920

template<bool TOF32>
__global__ __launch_bounds__(256) void gemm_mma(
    const __nv_bfloat16* __restrict__ Ahi, const __nv_bfloat16* __restrict__ Alo,
    const __nv_bfloat16* __restrict__ Bhi, const __nv_bfloat16* __restrict__ Blo,
    const float* __restrict__ bias, float* __restrict__ Cf,
    __nv_bfloat16* __restrict__ Chi, __nv_bfloat16* __restrict__ Clo,
    int ldc, int qscale)
{
    extern __shared__ char smc[];
    const uint32_t sb = smem_u32(smc);
    const int tid = threadIdx.x, lane = tid & 31, wid = tid >> 5;
    const int wm = wid >> 1, wn = wid & 1;
    const int g = lane >> 2, tg = lane & 3;
    const int brow = blockIdx.y * 128, bcol = blockIdx.x * 128;
    const int lr = tid >> 2, lq = tid & 3;

    auto issue = [&](int buf, int kc) {
        #pragma unroll
        for (int rep = 0; rep < 2; rep++) {
            int row = lr + rep * 64;
            size_t ga = (size_t)(brow + row) * DM + kc + lq * 8;
            size_t gb = (size_t)(bcol + row) * DM + kc + lq * 8;
            uint32_t off = sb + (uint32_t)buf * 4u * TSZ
                         + (uint32_t)(row * 40 + lq * 8) * 2u;
            CP16(off,            Ahi + ga);
            CP16(off + TSZ,      Alo + ga);
            CP16(off + 2u * TSZ, Bhi + gb);
            CP16(off + 3u * TSZ, Blo + gb);
        }
        CP_COMMIT;
    };

    float acc[2][8][4];
    #pragma unroll
    for (int a = 0; a < 2; a++)
        #pragma unroll
        for (int b = 0; b < 8; b++)
            #pragma unroll
            for (int c = 0; c < 4; c++) acc[a][b][c] = 0.f;

    issue(0, 0);

    for (int c = 0; c < 32; c++) {
        CP_WAIT0;
        __syncthreads();
        if (c < 31) issue((c + 1) & 1, (c + 1) * 32);
        const uint32_t tb = sb + (uint32_t)(c & 1) * 4u * TSZ;

        #pragma unroll
        for (int kk = 0; kk < 32; kk += 16) {
            uint32_t ah[2][4], al[2][4], bh[8][2], bl[8][2];
            #pragma unroll
            for (int fm = 0; fm < 2; fm++) {
                uint32_t ra = (uint32_t)((wm * 32 + fm * 16 + (lane & 7)
                              + 8 * ((lane >> 3) & 1)) * 40
                              + kk + 8 * (lane >> 4)) * 2u;
                ldm_x4(ah[fm], tb + ra);
                ldm_x4(al[fm], tb + TSZ + ra);
            }
            #pragma unroll
            for (int i = 0; i < 4; i++) {
                uint32_t rb = (uint32_t)((wn * 64 + i * 16 + (lane & 7)
                              + 8 * (lane >> 4)) * 40
                              + kk + 8 * ((lane >> 3) & 1)) * 2u;
                uint32_t t4[4];
                ldm_x4(t4, tb + 2u * TSZ + rb);
                bh[2*i][0] = t4[0]; bh[2*i][1] = t4[1];
                bh[2*i+1][0] = t4[2]; bh[2*i+1][1] = t4[3];
                ldm_x4(t4, tb + 3u * TSZ + rb);
                bl[2*i][0] = t4[0]; bl[2*i][1] = t4[1];
                bl[2*i+1][0] = t4[2]; bl[2*i+1][1] = t4[3];
            }
            #pragma unroll
            for (int fm = 0; fm < 2; fm++)
                #pragma unroll
                for (int fn = 0; fn < 8; fn++) {
                    mma_bf16(acc[fm][fn], ah[fm], bh[fn]);
                    mma_bf16(acc[fm][fn], ah[fm], bl[fn]);
                    mma_bf16(acc[fm][fn], al[fm], bh[fn]);
                }
        }
    }

    #pragma unroll
    for (int fm = 0; fm < 2; fm++) {
        int row = brow + wm * 32 + fm * 16 + g;
        #pragma unroll
        for (int fn = 0; fn < 8; fn++) {
            int col = bcol + wn * 64 + fn * 8 + 2 * tg;
            float sc = (qscale && col < 1024) ? QSCALE : 1.0f;
            float b0 = bias[col], b1 = bias[col + 1];
            float v0 = (acc[fm][fn][0] + b0) * sc;
            float v1 = (acc[fm][fn][1] + b1) * sc;
            float v2 = (acc[fm][fn][2] + b0) * sc;
            float v3 = (acc[fm][fn][3] + b1) * sc;
            if (TOF32) {
                *(float2*)&Cf[(size_t)row * ldc + col]       = make_float2(v0, v1);
                *(float2*)&Cf[(size_t)(row + 8) * ldc + col] = make_float2(v2, v3);
            } else {
                store_split(Chi, Clo, (size_t)row * ldc + col,       v0, v1);
                store_split(Chi, Clo, (size_t)(row + 8) * ldc + col, v2, v3);
            }
        }
    }
}

// ---------------------------------------------------------------------------
// Flash attention on mma.sync, split-bf16 x3 (R3 shape: Br=Bc=64, 128 thr,
// 4 CTAs/SM). Descending-qb order; softmax in exp2 domain (Q pre-scaled).
// ---------------------------------------------------------------------------
#define AST 72        // b16 row stride (144B: 16B-aligned, ldmatrix conflict-free)
#define QHI_O 0u
#define QLO_O 9216u
#define KHI_O 18432u
#define KLO_O 27648u
#define VHI_O 36864u
#define VLO_O 46080u
#define ATTN_SMEM 55296

__global__ __launch_bounds__(128) void attn_mma()
{
    extern __shared__ char smc[];
    const uint32_t sb = smem_u32(smc);
    const int tid = threadIdx.x, lane = tid & 31, w = tid >> 5;
    const int g = lane >> 2, tg = lane & 3;
    const int qb = (int)gridDim.x - 1 - (int)blockIdx.x;   // heavy blocks first
    const int h = blockIdx.y, b = blockIdx.z;
    const int qbase = qb * 64;
    const size_t rowb = (size_t)b * SEQ;
    const int hoff = h * HD;

    // load Q tile (hi/lo), 64 rows x 64 bf16
    #pragma unroll
    for (int i = 0; i < 4; i++) {
        int slot = tid + 128 * i;
        int r = slot >> 3, q8 = slot & 7;
        size_t go = (rowb + qbase + r) * 3072 + hoff + q8 * 8;
        uint32_t so = (uint32_t)(r * AST + q8 * 8) * 2u;
        *(uint4*)(smc + QHI_O + so) = *(const uint4*)(g_QKVhi + go);
        *(uint4*)(smc + QLO_O + so) = *(const uint4*)(g_QKVlo + go);
    }

    float o[8][4];
    #pragma unroll
    for (int fn = 0; fn < 8; fn++)
        #pragma unroll
        for (int c = 0; c < 4; c++) o[fn][c] = 0.f;
    float m0 = -1e30f, m1 = -1e30f, l0 = 0.f, l1 = 0.f;

    for (int kb = 0; kb <= qb; kb++) {
        __syncthreads();   // Q visible (first) / prev compute done (later)
        const int kbase = kb * 64;
        #pragma unroll
        for (int i = 0; i < 4; i++) {
            int slot = tid + 128 * i;
            int r = slot >> 3, q8 = slot & 7;
            size_t go = (rowb + kbase + r) * 3072 + hoff + q8 * 8;
            uint32_t so = (uint32_t)(r * AST + q8 * 8) * 2u;
            *(uint4*)(smc + KHI_O + so) = *(const uint4*)(g_QKVhi + go + 1024);
            *(uint4*)(smc + KLO_O + so) = *(const uint4*)(g_QKVlo + go + 1024);
            *(uint4*)(smc + VHI_O + so) = *(const uint4*)(g_QKVhi + go + 2048);
            *(uint4*)(smc + VLO_O + so) = *(const uint4*)(g_QKVlo + go + 2048);
        }
        __syncthreads();

        // ---- S = Q @ K^T (S already in log2 units: Q pre-scaled) ----
        float s[8][4];
        #pragma unroll
        for (int fn = 0; fn < 8; fn++)
            #pragma unroll
            for (int c = 0; c < 4; c++) s[fn][c] = 0.f;

        #pragma unroll
        for (int kk = 0; kk < 64; kk += 16) {
            uint32_t qh[4], ql[4];
            uint32_t ra = sb + (uint32_t)((w * 16 + (lane & 7)
                          + 8 * ((lane >> 3) & 1)) * AST
                          + kk + 8 * (lane >> 4)) * 2u;
            ldm_x4(qh, ra + QHI_O);
            ldm_x4(ql, ra + QLO_O);
            #pragma unroll
            for (int i = 0; i < 4; i++) {
                uint32_t rb = sb + (uint32_t)((i * 16 + (lane & 7)
                              + 8 * (lane >> 4)) * AST
                              + kk + 8 * ((lane >> 3) & 1)) * 2u;
                uint32_t th[4], tl[4];
                ldm_x4(th, rb + KHI_O);
                ldm_x4(tl, rb + KLO_O);
                mma_bf16(s[2*i],   qh, th);
                mma_bf16(s[2*i],   qh, tl);
                mma_bf16(s[2*i],   ql, th);
                mma_bf16(s[2*i+1], qh, th + 2);
                mma_bf16(s[2*i+1], qh, tl + 2);
                mma_bf16(s[2*i+1], ql, th + 2);
            }
        }

        // ---- causal mask on diagonal tile ----
        if (kb == qb) {
            const int lr0 = w * 16 + g, lr1 = lr0 + 8;
            #pragma unroll
            for (int fn = 0; fn < 8; fn++) {
                int c0 = fn * 8 + 2 * tg;
                if (c0     > lr0) s[fn][0] = -1e30f;
                if (c0 + 1 > lr0) s[fn][1] = -1e30f;
                if (c0     > lr1) s[fn][2] = -1e30f;
                if (c0 + 1 > lr1) s[fn][3] = -1e30f;
            }
        }

        // ---- online softmax (exp2 domain) ----
        float rm0 = -1e30f, rm1 = -1e30f;
        #pragma unroll
        for (int fn = 0; fn < 8; fn++) {
            rm0 = fmaxf(rm0, fmaxf(s[fn][0], s[fn][1]));
            rm1 = fmaxf(rm1, fmaxf(s[fn][2], s[fn][3]));
        }
        rm0 = fmaxf(rm0, __shfl_xor_sync(0xffffffffu, rm0, 1));
        rm0 = fmaxf(rm0, __shfl_xor_sync(0xffffffffu, rm0, 2));
        rm1 = fmaxf(rm1, __shfl_xor_sync(0xffffffffu, rm1, 1));
        rm1 = fmaxf(rm1, __shfl_xor_sync(0xffffffffu, rm1, 2));
        const float mn0 = fmaxf(m0, rm0), mn1 = fmaxf(m1, rm1);
        const float c0 = ex2f(m0 - mn0), c1 = ex2f(m1 - mn1);
        m0 = mn0; m1 = mn1;
        float sum0 = 0.f, sum1 = 0.f;
        #pragma unroll
        for (int fn = 0; fn < 8; fn++) {
            s[fn][0] = ex2f(s[fn][0] - mn0); sum0 += s[fn][0];
            s[fn][1] = ex2f(s[fn][1] - mn0); sum0 += s[fn][1];
            s[fn][2] = ex2f(s[fn][2] - mn1); sum1 += s[fn][2];
            s[fn][3] = ex2f(s[fn][3] - mn1); sum1 += s[fn][3];
        }
        sum0 += __shfl_xor_sync(0xffffffffu, sum0, 1);
        sum0 += __shfl_xor_sync(0xffffffffu, sum0, 2);
        sum1 += __shfl_xor_sync(0xffffffffu, sum1, 1);
        sum1 += __shfl_xor_sync(0xffffffffu, sum1, 2);
        l0 = l0 * c0 + sum0;
        l1 = l1 * c1 + sum1;
        #pragma unroll
        for (int fn = 0; fn < 8; fn++) {
            o[fn][0] *= c0; o[fn][1] *= c0;
            o[fn][2] *= c1; o[fn][3] *= c1;
        }

        // ---- O += P @ V  (P from S regs; V via ldmatrix.trans) ----
        #pragma unroll
        for (int kk = 0; kk < 64; kk += 16) {
            const int f0 = kk >> 3, f1 = f0 + 1;
            uint32_t ph[4], pl[4];
            split2(s[f0][0], s[f0][1], ph[0], pl[0]);
            split2(s[f0][2], s[f0][3], ph[1], pl[1]);
            split2(s[f1][0], s[f1][1], ph[2], pl[2]);
            split2(s[f1][2], s[f1][3], ph[3], pl[3]);
            uint32_t rv = sb + (uint32_t)((kk + (lane & 15)) * AST) * 2u;
            #pragma unroll
            for (int fn = 0; fn < 8; fn++) {
                uint32_t vh[2], vl[2];
                ldm_x2t(vh, rv + VHI_O + (uint32_t)(fn * 16));
                ldm_x2t(vl, rv + VLO_O + (uint32_t)(fn * 16));
                mma_bf16(o[fn], ph, vh);
                mma_bf16(o[fn], ph, vl);
                mma_bf16(o[fn], pl, vh);
            }
        }
    }

    // ---- epilogue: normalize, split-store AO ----
    const float i0 = 1.f / l0, i1 = 1.f / l1;
    const size_t r0 = rowb + qbase + w * 16 + g;
    #pragma unroll
    for (int fn = 0; fn < 8; fn++) {
        int col = hoff + fn * 8 + 2 * tg;
        store_split(g_AOhi, g_AOlo, r0 * DM + col,       o[fn][0] * i0, o[fn][1] * i0);
        store_split(g_AOhi, g_AOlo, (r0 + 8) * DM + col, o[fn][2] * i1, o[fn][3] * i1);
    }
}

// ---------------------------------------------------------------------------
// Launch
// ---------------------------------------------------------------------------
extern "C" void kernel_launch(void* const* d_in, const int* in_sizes, int n_in,
                              void* d_out, int out_size)
{
    const float* X  = (const float*)d_in[0];
    const float* Wq = (const float*)d_in[1];
    const float* bq = (const float*)d_in[2];
    const float* Wk = (const float*)d_in[3];
    const float* bk = (const float*)d_in[4];
    const float* Wv = (const float*)d_in[5];
    const float* bv = (const float*)d_in[6];
    const float* Wo = (const float*)d_in[7];
    const float* bo = (const float*)d_in[8];
    float* out = (float*)d_out;

    __nv_bfloat16 *Xhi, *Xlo, *WThi, *WTlo, *QKVhi, *QKVlo, *AOhi, *AOlo;
    float* biasP;
    cudaGetSymbolAddress((void**)&Xhi,   g_Xhi);
    cudaGetSymbolAddress((void**)&Xlo,   g_Xlo);
    cudaGetSymbolAddress((void**)&WThi,  g_WThi);
    cudaGetSymbolAddress((void**)&WTlo,  g_WTlo);
    cudaGetSymbolAddress((void**)&QKVhi, g_QKVhi);
    cudaGetSymbolAddress((void**)&QKVlo, g_QKVlo);
    cudaGetSymbolAddress((void**)&AOhi,  g_AOhi);
    cudaGetSymbolAddress((void**)&AOlo,  g_AOlo);
    cudaGetSymbolAddress((void**)&biasP, g_bias);

    cudaFuncSetAttribute(gemm_mma<false>,
        cudaFuncAttributeMaxDynamicSharedMemorySize, (int)GEMM_SMEM);
    cudaFuncSetAttribute(gemm_mma<true>,
        cudaFuncAttributeMaxDynamicSharedMemorySize, (int)GEMM_SMEM);
    cudaFuncSetAttribute(attn_mma,
        cudaFuncAttributeMaxDynamicSharedMemorySize, (int)ATTN_SMEM);

    const int n4 = MR * DM / 4;

    split_f32<<<(n4 + 255) / 256, 256>>>(X, Xhi, Xlo, n4);
    split_wT4<<<dim3(DM / 32, DM / 32, 4), dim3(32, 8)>>>(Wq, Wk, Wv, Wo, WThi, WTlo);
    concat_bias<<<16, 256>>>(bq, bk, bv, bo, biasP);

    // fused QKV projection (N=3072), Q region scaled by log2e/8, split-bf16 out
    gemm_mma<false><<<dim3(24, 32), 256, GEMM_SMEM>>>(
        Xhi, Xlo, WThi, WTlo, biasP, nullptr, QKVhi, QKVlo, 3072, 1);

    // causal attention (Br=Bc=64, 4 CTAs/SM), split-bf16 out
    attn_mma<<<dim3(SEQ / 64, NH, BATCH), 128, ATTN_SMEM>>>();

    // output projection, fp32 out
    const size_t WSZ = (size_t)DM * DM;
    gemm_mma<true><<<dim3(8, 32), 256, GEMM_SMEM>>>(
        AOhi, AOlo, WThi + 3 * WSZ, WTlo + 3 * WSZ, biasP + 3072,
        out, nullptr, nullptr, 1024, 0);
}

// round 7
// speedup vs baseline: 1.1702x; 1.1207x over previous
#include <cuda_runtime.h>
#include <cuda_bf16.h>
#include <math.h>
#include <stdint.h>

#define BATCH 2
#define SEQ   2048
#define DM    1024
#define NH    16
#define HD    64
#define MR    (BATCH*SEQ)   // 4096

// Q pre-scale: log2(e) / sqrt(64)  -> softmax works in exp2 domain
#define QSCALE 0.1803368801111244f

// ---------------------------------------------------------------------------
// Scratch (allocation-free rule: device globals)
// ---------------------------------------------------------------------------
__device__ __nv_bfloat16 g_Xhi[(size_t)MR * DM];
__device__ __nv_bfloat16 g_Xlo[(size_t)MR * DM];
// WT rows: 0-1023 WqT, 1024-2047 WkT, 2048-3071 WvT, 3072-4095 WoT  ([n][k])
__device__ __nv_bfloat16 g_WThi[(size_t)4096 * DM];
__device__ __nv_bfloat16 g_WTlo[(size_t)4096 * DM];
__device__ float         g_bias[4096];          // bq|bk|bv|bo
__device__ __nv_bfloat16 g_QKVhi[(size_t)MR * 3072];
__device__ __nv_bfloat16 g_QKVlo[(size_t)MR * 3072];
__device__ __nv_bfloat16 g_AOhi[(size_t)MR * DM];
__device__ __nv_bfloat16 g_AOlo[(size_t)MR * DM];

// ---------------------------------------------------------------------------
// PTX helpers (all sm_80-era: compile at compute_103)
// ---------------------------------------------------------------------------
__device__ __forceinline__ uint32_t smem_u32(const void* p) {
    uint32_t a;
    asm("{ .reg .u64 t; cvta.to.shared.u64 t, %1; cvt.u32.u64 %0, t; }"
        : "=r"(a) : "l"(p));
    return a;
}

__device__ __forceinline__ float ex2f(float x) {
    float y;
    asm("ex2.approx.f32 %0, %1;" : "=f"(y) : "f"(x));
    return y;
}

__device__ __forceinline__ void mma_bf16(float* d, const uint32_t* a, const uint32_t* b) {
    asm volatile(
        "mma.sync.aligned.m16n8k16.row.col.f32.bf16.bf16.f32 "
        "{%0,%1,%2,%3}, {%4,%5,%6,%7}, {%8,%9}, {%0,%1,%2,%3};"
        : "+f"(d[0]), "+f"(d[1]), "+f"(d[2]), "+f"(d[3])
        : "r"(a[0]), "r"(a[1]), "r"(a[2]), "r"(a[3]), "r"(b[0]), "r"(b[1]));
}

__device__ __forceinline__ void ldm_x4(uint32_t* r, uint32_t addr) {
    asm volatile("ldmatrix.sync.aligned.m8n8.x4.shared.b16 {%0,%1,%2,%3}, [%4];"
                 : "=r"(r[0]), "=r"(r[1]), "=r"(r[2]), "=r"(r[3]) : "r"(addr));
}
__device__ __forceinline__ void ldm_x2t(uint32_t* r, uint32_t addr) {
    asm volatile("ldmatrix.sync.aligned.m8n8.x2.trans.shared.b16 {%0,%1}, [%2];"
                 : "=r"(r[0]), "=r"(r[1]) : "r"(addr));
}

#define CP16(sm, g) \
    asm volatile("cp.async.cg.shared.global [%0], [%1], 16;" :: "r"(sm), "l"(g))
#define CP_COMMIT asm volatile("cp.async.commit_group;")
#define CP_WAIT0  asm volatile("cp.async.wait_group 0;" ::: "memory")

__device__ __forceinline__ void split2(float a, float b, uint32_t& hi, uint32_t& lo) {
    __nv_bfloat162 H = __floats2bfloat162_rn(a, b);
    float ra = a - __bfloat162float(H.x);
    float rb = b - __bfloat162float(H.y);
    __nv_bfloat162 L = __floats2bfloat162_rn(ra, rb);
    hi = *(uint32_t*)&H;
    lo = *(uint32_t*)&L;
}

__device__ __forceinline__ void store_split(__nv_bfloat16* Chi, __nv_bfloat16* Clo,
                                            size_t idx, float v0, float v1) {
    uint32_t h, l;
    split2(v0, v1, h, l);
    *(uint32_t*)(Chi + idx) = h;
    *(uint32_t*)(Clo + idx) = l;
}

// ---------------------------------------------------------------------------
// Conversion kernels
// ---------------------------------------------------------------------------
__global__ void split_f32(const float* __restrict__ src,
                          __nv_bfloat16* __restrict__ hi,
                          __nv_bfloat16* __restrict__ lo, int n4)
{
    int i = blockIdx.x * blockDim.x + threadIdx.x;
    if (i >= n4) return;
    float4 v = ((const float4*)src)[i];
    store_split(hi, lo, 4 * (size_t)i,     v.x, v.y);
    store_split(hi, lo, 4 * (size_t)i + 2, v.z, v.w);
}

// All four W [K][N] fp32 -> WT hi/lo [N][K] bf16 (transpose + split), fused
__global__ void split_wT4(const float* __restrict__ W0, const float* __restrict__ W1,
                          const float* __restrict__ W2, const float* __restrict__ W3,
                          __nv_bfloat16* __restrict__ Thi,
                          __nv_bfloat16* __restrict__ Tlo)
{
    __shared__ float t[32][33];
    const int z = blockIdx.z;
    const float* W = (z == 0) ? W0 : (z == 1) ? W1 : (z == 2) ? W2 : W3;
    __nv_bfloat16* thi = Thi + (size_t)z * DM * DM;
    __nv_bfloat16* tlo = Tlo + (size_t)z * DM * DM;
    const int k0 = blockIdx.y * 32, n0 = blockIdx.x * 32;
    const int tx = threadIdx.x, ty = threadIdx.y;
    #pragma unroll
    for (int i = ty; i < 32; i += 8)
        t[i][tx] = W[(size_t)(k0 + i) * DM + n0 + tx];
    __syncthreads();
    #pragma unroll
    for (int i = ty; i < 32; i += 8) {
        float v = t[tx][i];
        __nv_bfloat16 h = __float2bfloat16_rn(v);
        thi[(size_t)(n0 + i) * DM + k0 + tx] = h;
        tlo[(size_t)(n0 + i) * DM + k0 + tx] =
            __float2bfloat16_rn(v - __bfloat162float(h));
    }
}

__global__ void concat_bias(const float* bq, const float* bk, const float* bv,
                            const float* bo, float* dst)
{
    int i = blockIdx.x * blockDim.x + threadIdx.x;
    if (i >= 4096) return;
    float v;
    if      (i < 1024) v = bq[i];
    else if (i < 2048) v = bk[i - 1024];
    else if (i < 3072) v = bv[i - 2048];
    else               v = bo[i - 3072];
    dst[i] = v;
}

// ---------------------------------------------------------------------------
// Split-bf16 x3 GEMM on mma.sync:  C[M,N] = A[M,1024] @ B^T + bias
// CTA 128x128, BK=32, 8 warps (4x2, warp tile 32x64), cp.async double buffer.
// B fragments loaded on demand (8 live regs) -> fits 128 regs -> 2 CTAs/SM.
// ---------------------------------------------------------------------------
#define TSZ 10240u   // one 128x40-b16 tile in bytes
#define GEMM_SMEM (8u * TSZ)   // 81920

template<bool TOF32>
__global__ __launch_bounds__(256, 2) void gemm_mma(
    const __nv_bfloat16* __restrict__ Ahi, const __nv_bfloat16* __restrict__ Alo,
    const __nv_bfloat16* __restrict__ Bhi, const __nv_bfloat16* __restrict__ Blo,
    const float* __restrict__ bias, float* __restrict__ Cf,
    __nv_bfloat16* __restrict__ Chi, __nv_bfloat16* __restrict__ Clo,
    int ldc, int qscale)
{
    extern __shared__ char smc[];
    const uint32_t sb = smem_u32(smc);
    const int tid = threadIdx.x, lane = tid & 31, wid = tid >> 5;
    const int wm = wid >> 1, wn = wid & 1;
    const int g = lane >> 2, tg = lane & 3;
    const int brow = blockIdx.y * 128, bcol = blockIdx.x * 128;
    const int lr = tid >> 2, lq = tid & 3;

    auto issue = [&](int buf, int kc) {
        #pragma unroll
        for (int rep = 0; rep < 2; rep++) {
            int row = lr + rep * 64;
            size_t ga = (size_t)(brow + row) * DM + kc + lq * 8;
            size_t gb = (size_t)(bcol + row) * DM + kc + lq * 8;
            uint32_t off = sb + (uint32_t)buf * 4u * TSZ
                         + (uint32_t)(row * 40 + lq * 8) * 2u;
            CP16(off,            Ahi + ga);
            CP16(off + TSZ,      Alo + ga);
            CP16(off + 2u * TSZ, Bhi + gb);
            CP16(off + 3u * TSZ, Blo + gb);
        }
        CP_COMMIT;
    };

    float acc[2][8][4];
    #pragma unroll
    for (int a = 0; a < 2; a++)
        #pragma unroll
        for (int b = 0; b < 8; b++)
            #pragma unroll
            for (int c = 0; c < 4; c++) acc[a][b][c] = 0.f;

    issue(0, 0);

    for (int c = 0; c < 32; c++) {
        CP_WAIT0;
        __syncthreads();
        if (c < 31) issue((c + 1) & 1, (c + 1) * 32);
        const uint32_t tb = sb + (uint32_t)(c & 1) * 4u * TSZ;

        #pragma unroll
        for (int kk = 0; kk < 32; kk += 16) {
            uint32_t ah[2][4], al[2][4];
            #pragma unroll
            for (int fm = 0; fm < 2; fm++) {
                uint32_t ra = (uint32_t)((wm * 32 + fm * 16 + (lane & 7)
                              + 8 * ((lane >> 3) & 1)) * 40
                              + kk + 8 * (lane >> 4)) * 2u;
                ldm_x4(ah[fm], tb + ra);
                ldm_x4(al[fm], tb + TSZ + ra);
            }
            #pragma unroll
            for (int i = 0; i < 4; i++) {
                uint32_t rb = (uint32_t)((wn * 64 + i * 16 + (lane & 7)
                              + 8 * (lane >> 4)) * 40
                              + kk + 8 * ((lane >> 3) & 1)) * 2u;
                uint32_t th[4], tl[4];
                ldm_x4(th, tb + 2u * TSZ + rb);
                ldm_x4(tl, tb + 3u * TSZ + rb);
                #pragma unroll
                for (int fm = 0; fm < 2; fm++) {
                    mma_bf16(acc[fm][2*i],   ah[fm], th);
                    mma_bf16(acc[fm][2*i],   ah[fm], tl);
                    mma_bf16(acc[fm][2*i],   al[fm], th);
                    mma_bf16(acc[fm][2*i+1], ah[fm], th + 2);
                    mma_bf16(acc[fm][2*i+1], ah[fm], tl + 2);
                    mma_bf16(acc[fm][2*i+1], al[fm], th + 2);
                }
            }
        }
    }

    #pragma unroll
    for (int fm = 0; fm < 2; fm++) {
        int row = brow + wm * 32 + fm * 16 + g;
        #pragma unroll
        for (int fn = 0; fn < 8; fn++) {
            int col = bcol + wn * 64 + fn * 8 + 2 * tg;
            float sc = (qscale && col < 1024) ? QSCALE : 1.0f;
            float b0 = bias[col], b1 = bias[col + 1];
            float v0 = (acc[fm][fn][0] + b0) * sc;
            float v1 = (acc[fm][fn][1] + b1) * sc;
            float v2 = (acc[fm][fn][2] + b0) * sc;
            float v3 = (acc[fm][fn][3] + b1) * sc;
            if (TOF32) {
                *(float2*)&Cf[(size_t)row * ldc + col]       = make_float2(v0, v1);
                *(float2*)&Cf[(size_t)(row + 8) * ldc + col] = make_float2(v2, v3);
            } else {
                store_split(Chi, Clo, (size_t)row * ldc + col,       v0, v1);
                store_split(Chi, Clo, (size_t)(row + 8) * ldc + col, v2, v3);
            }
        }
    }
}

// ---------------------------------------------------------------------------
// Flash attention on mma.sync, split-bf16 x3 (Br=Bc=64, 128 thr, 4 CTAs/SM).
// Descending-qb order; softmax in exp2 domain (Q pre-scaled).
// ---------------------------------------------------------------------------
#define AST 72        // b16 row stride (144B: 16B-aligned, ldmatrix conflict-free)
#define QHI_O 0u
#define QLO_O 9216u
#define KHI_O 18432u
#define KLO_O 27648u
#define VHI_O 36864u
#define VLO_O 46080u
#define ATTN_SMEM 55296

__global__ __launch_bounds__(128) void attn_mma()
{
    extern __shared__ char smc[];
    const uint32_t sb = smem_u32(smc);
    const int tid = threadIdx.x, lane = tid & 31, w = tid >> 5;
    const int g = lane >> 2, tg = lane & 3;
    const int qb = (int)gridDim.x - 1 - (int)blockIdx.x;   // heavy blocks first
    const int h = blockIdx.y, b = blockIdx.z;
    const int qbase = qb * 64;
    const size_t rowb = (size_t)b * SEQ;
    const int hoff = h * HD;

    // load Q tile (hi/lo), 64 rows x 64 bf16
    #pragma unroll
    for (int i = 0; i < 4; i++) {
        int slot = tid + 128 * i;
        int r = slot >> 3, q8 = slot & 7;
        size_t go = (rowb + qbase + r) * 3072 + hoff + q8 * 8;
        uint32_t so = (uint32_t)(r * AST + q8 * 8) * 2u;
        *(uint4*)(smc + QHI_O + so) = *(const uint4*)(g_QKVhi + go);
        *(uint4*)(smc + QLO_O + so) = *(const uint4*)(g_QKVlo + go);
    }

    float o[8][4];
    #pragma unroll
    for (int fn = 0; fn < 8; fn++)
        #pragma unroll
        for (int c = 0; c < 4; c++) o[fn][c] = 0.f;
    float m0 = -1e30f, m1 = -1e30f, l0 = 0.f, l1 = 0.f;

    for (int kb = 0; kb <= qb; kb++) {
        __syncthreads();   // Q visible (first) / prev compute done (later)
        const int kbase = kb * 64;
        #pragma unroll
        for (int i = 0; i < 4; i++) {
            int slot = tid + 128 * i;
            int r = slot >> 3, q8 = slot & 7;
            size_t go = (rowb + kbase + r) * 3072 + hoff + q8 * 8;
            uint32_t so = (uint32_t)(r * AST + q8 * 8) * 2u;
            *(uint4*)(smc + KHI_O + so) = *(const uint4*)(g_QKVhi + go + 1024);
            *(uint4*)(smc + KLO_O + so) = *(const uint4*)(g_QKVlo + go + 1024);
            *(uint4*)(smc + VHI_O + so) = *(const uint4*)(g_QKVhi + go + 2048);
            *(uint4*)(smc + VLO_O + so) = *(const uint4*)(g_QKVlo + go + 2048);
        }
        __syncthreads();

        // ---- S = Q @ K^T (S already in log2 units: Q pre-scaled) ----
        float s[8][4];
        #pragma unroll
        for (int fn = 0; fn < 8; fn++)
            #pragma unroll
            for (int c = 0; c < 4; c++) s[fn][c] = 0.f;

        #pragma unroll
        for (int kk = 0; kk < 64; kk += 16) {
            uint32_t qh[4], ql[4];
            uint32_t ra = sb + (uint32_t)((w * 16 + (lane & 7)
                          + 8 * ((lane >> 3) & 1)) * AST
                          + kk + 8 * (lane >> 4)) * 2u;
            ldm_x4(qh, ra + QHI_O);
            ldm_x4(ql, ra + QLO_O);
            #pragma unroll
            for (int i = 0; i < 4; i++) {
                uint32_t rb = sb + (uint32_t)((i * 16 + (lane & 7)
                              + 8 * (lane >> 4)) * AST
                              + kk + 8 * ((lane >> 3) & 1)) * 2u;
                uint32_t th[4], tl[4];
                ldm_x4(th, rb + KHI_O);
                ldm_x4(tl, rb + KLO_O);
                mma_bf16(s[2*i],   qh, th);
                mma_bf16(s[2*i],   qh, tl);
                mma_bf16(s[2*i],   ql, th);
                mma_bf16(s[2*i+1], qh, th + 2);
                mma_bf16(s[2*i+1], qh, tl + 2);
                mma_bf16(s[2*i+1], ql, th + 2);
            }
        }

        // ---- causal mask on diagonal tile ----
        if (kb == qb) {
            const int lr0 = w * 16 + g, lr1 = lr0 + 8;
            #pragma unroll
            for (int fn = 0; fn < 8; fn++) {
                int c0 = fn * 8 + 2 * tg;
                if (c0     > lr0) s[fn][0] = -1e30f;
                if (c0 + 1 > lr0) s[fn][1] = -1e30f;
                if (c0     > lr1) s[fn][2] = -1e30f;
                if (c0 + 1 > lr1) s[fn][3] = -1e30f;
            }
        }

        // ---- online softmax (exp2 domain) ----
        float rm0 = -1e30f, rm1 = -1e30f;
        #pragma unroll
        for (int fn = 0; fn < 8; fn++) {
            rm0 = fmaxf(rm0, fmaxf(s[fn][0], s[fn][1]));
            rm1 = fmaxf(rm1, fmaxf(s[fn][2], s[fn][3]));
        }
        rm0 = fmaxf(rm0, __shfl_xor_sync(0xffffffffu, rm0, 1));
        rm0 = fmaxf(rm0, __shfl_xor_sync(0xffffffffu, rm0, 2));
        rm1 = fmaxf(rm1, __shfl_xor_sync(0xffffffffu, rm1, 1));
        rm1 = fmaxf(rm1, __shfl_xor_sync(0xffffffffu, rm1, 2));
        const float mn0 = fmaxf(m0, rm0), mn1 = fmaxf(m1, rm1);
        const float c0 = ex2f(m0 - mn0), c1 = ex2f(m1 - mn1);
        m0 = mn0; m1 = mn1;
        float sum0 = 0.f, sum1 = 0.f;
        #pragma unroll
        for (int fn = 0; fn < 8; fn++) {
            s[fn][0] = ex2f(s[fn][0] - mn0); sum0 += s[fn][0];
            s[fn][1] = ex2f(s[fn][1] - mn0); sum0 += s[fn][1];
            s[fn][2] = ex2f(s[fn][2] - mn1); sum1 += s[fn][2];
            s[fn][3] = ex2f(s[fn][3] - mn1); sum1 += s[fn][3];
        }
        sum0 += __shfl_xor_sync(0xffffffffu, sum0, 1);
        sum0 += __shfl_xor_sync(0xffffffffu, sum0, 2);
        sum1 += __shfl_xor_sync(0xffffffffu, sum1, 1);
        sum1 += __shfl_xor_sync(0xffffffffu, sum1, 2);
        l0 = l0 * c0 + sum0;
        l1 = l1 * c1 + sum1;
        #pragma unroll
        for (int fn = 0; fn < 8; fn++) {
            o[fn][0] *= c0; o[fn][1] *= c0;
            o[fn][2] *= c1; o[fn][3] *= c1;
        }

        // ---- O += P @ V  (P from S regs; V via ldmatrix.trans) ----
        #pragma unroll
        for (int kk = 0; kk < 64; kk += 16) {
            const int f0 = kk >> 3, f1 = f0 + 1;
            uint32_t ph[4], pl[4];
            split2(s[f0][0], s[f0][1], ph[0], pl[0]);
            split2(s[f0][2], s[f0][3], ph[1], pl[1]);
            split2(s[f1][0], s[f1][1], ph[2], pl[2]);
            split2(s[f1][2], s[f1][3], ph[3], pl[3]);
            uint32_t rv = sb + (uint32_t)((kk + (lane & 15)) * AST) * 2u;
            #pragma unroll
            for (int fn = 0; fn < 8; fn++) {
                uint32_t vh[2], vl[2];
                ldm_x2t(vh, rv + VHI_O + (uint32_t)(fn * 16));
                ldm_x2t(vl, rv + VLO_O + (uint32_t)(fn * 16));
                mma_bf16(o[fn], ph, vh);
                mma_bf16(o[fn], ph, vl);
                mma_bf16(o[fn], pl, vh);
            }
        }
    }

    // ---- epilogue: normalize, split-store AO ----
    const float i0 = 1.f / l0, i1 = 1.f / l1;
    const size_t r0 = rowb + qbase + w * 16 + g;
    #pragma unroll
    for (int fn = 0; fn < 8; fn++) {
        int col = hoff + fn * 8 + 2 * tg;
        store_split(g_AOhi, g_AOlo, r0 * DM + col,       o[fn][0] * i0, o[fn][1] * i0);
        store_split(g_AOhi, g_AOlo, (r0 + 8) * DM + col, o[fn][2] * i1, o[fn][3] * i1);
    }
}

// ---------------------------------------------------------------------------
// Launch
// ---------------------------------------------------------------------------
extern "C" void kernel_launch(void* const* d_in, const int* in_sizes, int n_in,
                              void* d_out, int out_size)
{
    const float* X  = (const float*)d_in[0];
    const float* Wq = (const float*)d_in[1];
    const float* bq = (const float*)d_in[2];
    const float* Wk = (const float*)d_in[3];
    const float* bk = (const float*)d_in[4];
    const float* Wv = (const float*)d_in[5];
    const float* bv = (const float*)d_in[6];
    const float* Wo = (const float*)d_in[7];
    const float* bo = (const float*)d_in[8];
    float* out = (float*)d_out;

    __nv_bfloat16 *Xhi, *Xlo, *WThi, *WTlo, *QKVhi, *QKVlo, *AOhi, *AOlo;
    float* biasP;
    cudaGetSymbolAddress((void**)&Xhi,   g_Xhi);
    cudaGetSymbolAddress((void**)&Xlo,   g_Xlo);
    cudaGetSymbolAddress((void**)&WThi,  g_WThi);
    cudaGetSymbolAddress((void**)&WTlo,  g_WTlo);
    cudaGetSymbolAddress((void**)&QKVhi, g_QKVhi);
    cudaGetSymbolAddress((void**)&QKVlo, g_QKVlo);
    cudaGetSymbolAddress((void**)&AOhi,  g_AOhi);
    cudaGetSymbolAddress((void**)&AOlo,  g_AOlo);
    cudaGetSymbolAddress((void**)&biasP, g_bias);

    cudaFuncSetAttribute(gemm_mma<false>,
        cudaFuncAttributeMaxDynamicSharedMemorySize, (int)GEMM_SMEM);
    cudaFuncSetAttribute(gemm_mma<true>,
        cudaFuncAttributeMaxDynamicSharedMemorySize, (int)GEMM_SMEM);
    cudaFuncSetAttribute(attn_mma,
        cudaFuncAttributeMaxDynamicSharedMemorySize, (int)ATTN_SMEM);

    const int n4 = MR * DM / 4;

    split_f32<<<(n4 + 255) / 256, 256>>>(X, Xhi, Xlo, n4);
    split_wT4<<<dim3(DM / 32, DM / 32, 4), dim3(32, 8)>>>(Wq, Wk, Wv, Wo, WThi, WTlo);
    concat_bias<<<16, 256>>>(bq, bk, bv, bo, biasP);

    // fused QKV projection (N=3072), Q region scaled by log2e/8, split-bf16 out
    gemm_mma<false><<<dim3(24, 32), 256, GEMM_SMEM>>>(
        Xhi, Xlo, WThi, WTlo, biasP, nullptr, QKVhi, QKVlo, 3072, 1);

    // causal attention (Br=Bc=64, 4 CTAs/SM), split-bf16 out
    attn_mma<<<dim3(SEQ / 64, NH, BATCH), 128, ATTN_SMEM>>>();

    // output projection, fp32 out
    const size_t WSZ = (size_t)DM * DM;
    gemm_mma<true><<<dim3(8, 32), 256, GEMM_SMEM>>>(
        AOhi, AOlo, WThi + 3 * WSZ, WTlo + 3 * WSZ, biasP + 3072,
        out, nullptr, nullptr, 1024, 0);
}

// round 8
// speedup vs baseline: 1.7476x; 1.4934x over previous
#include <cuda_runtime.h>
#include <cuda_fp16.h>
#include <math.h>
#include <stdint.h>

#define BATCH 2
#define SEQ   2048
#define DM    1024
#define NH    16
#define HD    64
#define MR    (BATCH*SEQ)   // 4096

// Q pre-scale: log2(e) / sqrt(64)  -> softmax works in exp2 domain
#define QSCALE 0.1803368801111244f

// ---------------------------------------------------------------------------
// Scratch (allocation-free rule: device globals)
// ---------------------------------------------------------------------------
__device__ __half g_Xhi[(size_t)MR * DM];
__device__ __half g_Xlo[(size_t)MR * DM];
// WT rows: 0-1023 WqT, 1024-2047 WkT, 2048-3071 WvT, 3072-4095 WoT  ([n][k]) fp16
__device__ __half g_WT[(size_t)4096 * DM];
__device__ float  g_bias[4096];          // bq|bk|bv|bo
__device__ __half g_QKVhi[(size_t)MR * 3072];
__device__ __half g_QKVlo[(size_t)MR * 3072];
__device__ __half g_AOhi[(size_t)MR * DM];
__device__ __half g_AOlo[(size_t)MR * DM];

// ---------------------------------------------------------------------------
// PTX helpers (all sm_80-era: compile at compute_103)
// ---------------------------------------------------------------------------
__device__ __forceinline__ uint32_t smem_u32(const void* p) {
    uint32_t a;
    asm("{ .reg .u64 t; cvta.to.shared.u64 t, %1; cvt.u32.u64 %0, t; }"
        : "=r"(a) : "l"(p));
    return a;
}

__device__ __forceinline__ float ex2f(float x) {
    float y;
    asm("ex2.approx.f32 %0, %1;" : "=f"(y) : "f"(x));
    return y;
}

__device__ __forceinline__ void mma_f16(float* d, const uint32_t* a, const uint32_t* b) {
    asm volatile(
        "mma.sync.aligned.m16n8k16.row.col.f32.f16.f16.f32 "
        "{%0,%1,%2,%3}, {%4,%5,%6,%7}, {%8,%9}, {%0,%1,%2,%3};"
        : "+f"(d[0]), "+f"(d[1]), "+f"(d[2]), "+f"(d[3])
        : "r"(a[0]), "r"(a[1]), "r"(a[2]), "r"(a[3]), "r"(b[0]), "r"(b[1]));
}

__device__ __forceinline__ void ldm_x4(uint32_t* r, uint32_t addr) {
    asm volatile("ldmatrix.sync.aligned.m8n8.x4.shared.b16 {%0,%1,%2,%3}, [%4];"
                 : "=r"(r[0]), "=r"(r[1]), "=r"(r[2]), "=r"(r[3]) : "r"(addr));
}
__device__ __forceinline__ void ldm_x2t(uint32_t* r, uint32_t addr) {
    asm volatile("ldmatrix.sync.aligned.m8n8.x2.trans.shared.b16 {%0,%1}, [%2];"
                 : "=r"(r[0]), "=r"(r[1]) : "r"(addr));
}

#define CP16(sm, g) \
    asm volatile("cp.async.cg.shared.global [%0], [%1], 16;" :: "r"(sm), "l"(g))
#define CP_COMMIT asm volatile("cp.async.commit_group;")
#define CP_WAIT0  asm volatile("cp.async.wait_group 0;" ::: "memory")

// fp16 hi/lo split of a float pair (hi exact-to-2^-11, lo = residual)
__device__ __forceinline__ void split2h(float a, float b, uint32_t& hi, uint32_t& lo) {
    __half2 H = __floats2half2_rn(a, b);
    float ra = a - __low2float(H);
    float rb = b - __high2float(H);
    __half2 L = __floats2half2_rn(ra, rb);
    hi = *(uint32_t*)&H;
    lo = *(uint32_t*)&L;
}

__device__ __forceinline__ void store_splith(__half* Chi, __half* Clo,
                                             size_t idx, float v0, float v1) {
    uint32_t h, l;
    split2h(v0, v1, h, l);
    *(uint32_t*)(Chi + idx) = h;
    *(uint32_t*)(Clo + idx) = l;
}

// ---------------------------------------------------------------------------
// Conversion kernels
// ---------------------------------------------------------------------------
__global__ void split_f32h(const float* __restrict__ src,
                           __half* __restrict__ hi,
                           __half* __restrict__ lo, int n4)
{
    int i = blockIdx.x * blockDim.x + threadIdx.x;
    if (i >= n4) return;
    float4 v = ((const float4*)src)[i];
    store_splith(hi, lo, 4 * (size_t)i,     v.x, v.y);
    store_splith(hi, lo, 4 * (size_t)i + 2, v.z, v.w);
}

// All four W [K][N] fp32 -> WT [N][K] fp16 (transpose, single precision term)
__global__ void split_wT4(const float* __restrict__ W0, const float* __restrict__ W1,
                          const float* __restrict__ W2, const float* __restrict__ W3,
                          __half* __restrict__ T)
{
    __shared__ float t[32][33];
    const int z = blockIdx.z;
    const float* W = (z == 0) ? W0 : (z == 1) ? W1 : (z == 2) ? W2 : W3;
    __half* th = T + (size_t)z * DM * DM;
    const int k0 = blockIdx.y * 32, n0 = blockIdx.x * 32;
    const int tx = threadIdx.x, ty = threadIdx.y;
    #pragma unroll
    for (int i = ty; i < 32; i += 8)
        t[i][tx] = W[(size_t)(k0 + i) * DM + n0 + tx];
    __syncthreads();
    #pragma unroll
    for (int i = ty; i < 32; i += 8)
        th[(size_t)(n0 + i) * DM + k0 + tx] = __float2half_rn(t[tx][i]);
}

__global__ void concat_bias(const float* bq, const float* bk, const float* bv,
                            const float* bo, float* dst)
{
    int i = blockIdx.x * blockDim.x + threadIdx.x;
    if (i >= 4096) return;
    float v;
    if      (i < 1024) v = bq[i];
    else if (i < 2048) v = bk[i - 1024];
    else if (i < 3072) v = bv[i - 2048];
    else               v = bo[i - 3072];
    dst[i] = v;
}

// ---------------------------------------------------------------------------
// Split-fp16 x2 GEMM on mma.sync:  C[M,N] = (Ahi+Alo)[M,1024] @ Bh^T + bias
// CTA 128x128, BK=32, 8 warps (4x2, warp tile 32x64), cp.async double buffer.
// 2 MMA terms per K step (A exact as hi+lo fp16; B single fp16).
// ---------------------------------------------------------------------------
#define TSZ 10240u   // one 128x40-b16 tile in bytes
#define GEMM_SMEM (6u * TSZ)   // 61440: 2 bufs x {Ah, Al, B}

template<bool TOF32>
__global__ __launch_bounds__(256, 2) void gemm_mma(
    const __half* __restrict__ Ahi, const __half* __restrict__ Alo,
    const __half* __restrict__ Bh,
    const float* __restrict__ bias, float* __restrict__ Cf,
    __half* __restrict__ Chi, __half* __restrict__ Clo,
    int ldc, int qscale)
{
    extern __shared__ char smc[];
    const uint32_t sb = smem_u32(smc);
    const int tid = threadIdx.x, lane = tid & 31, wid = tid >> 5;
    const int wm = wid >> 1, wn = wid & 1;
    const int g = lane >> 2, tg = lane & 3;
    const int brow = blockIdx.y * 128, bcol = blockIdx.x * 128;
    const int lr = tid >> 2, lq = tid & 3;

    auto issue = [&](int buf, int kc) {
        #pragma unroll
        for (int rep = 0; rep < 2; rep++) {
            int row = lr + rep * 64;
            size_t ga = (size_t)(brow + row) * DM + kc + lq * 8;
            size_t gb = (size_t)(bcol + row) * DM + kc + lq * 8;
            uint32_t off = sb + (uint32_t)buf * 3u * TSZ
                         + (uint32_t)(row * 40 + lq * 8) * 2u;
            CP16(off,            Ahi + ga);
            CP16(off + TSZ,      Alo + ga);
            CP16(off + 2u * TSZ, Bh + gb);
        }
        CP_COMMIT;
    };

    float acc[2][8][4];
    #pragma unroll
    for (int a = 0; a < 2; a++)
        #pragma unroll
        for (int b = 0; b < 8; b++)
            #pragma unroll
            for (int c = 0; c < 4; c++) acc[a][b][c] = 0.f;

    issue(0, 0);

    for (int c = 0; c < 32; c++) {
        CP_WAIT0;
        __syncthreads();
        if (c < 31) issue((c + 1) & 1, (c + 1) * 32);
        const uint32_t tb = sb + (uint32_t)(c & 1) * 3u * TSZ;

        #pragma unroll
        for (int kk = 0; kk < 32; kk += 16) {
            uint32_t ah[2][4], al[2][4];
            #pragma unroll
            for (int fm = 0; fm < 2; fm++) {
                uint32_t ra = (uint32_t)((wm * 32 + fm * 16 + (lane & 7)
                              + 8 * ((lane >> 3) & 1)) * 40
                              + kk + 8 * (lane >> 4)) * 2u;
                ldm_x4(ah[fm], tb + ra);
                ldm_x4(al[fm], tb + TSZ + ra);
            }
            #pragma unroll
            for (int i = 0; i < 4; i++) {
                uint32_t rb = (uint32_t)((wn * 64 + i * 16 + (lane & 7)
                              + 8 * (lane >> 4)) * 40
                              + kk + 8 * ((lane >> 3) & 1)) * 2u;
                uint32_t th[4];
                ldm_x4(th, tb + 2u * TSZ + rb);
                #pragma unroll
                for (int fm = 0; fm < 2; fm++) {
                    mma_f16(acc[fm][2*i],   ah[fm], th);
                    mma_f16(acc[fm][2*i],   al[fm], th);
                    mma_f16(acc[fm][2*i+1], ah[fm], th + 2);
                    mma_f16(acc[fm][2*i+1], al[fm], th + 2);
                }
            }
        }
    }

    #pragma unroll
    for (int fm = 0; fm < 2; fm++) {
        int row = brow + wm * 32 + fm * 16 + g;
        #pragma unroll
        for (int fn = 0; fn < 8; fn++) {
            int col = bcol + wn * 64 + fn * 8 + 2 * tg;
            float sc = (qscale && col < 1024) ? QSCALE : 1.0f;
            float b0 = bias[col], b1 = bias[col + 1];
            float v0 = (acc[fm][fn][0] + b0) * sc;
            float v1 = (acc[fm][fn][1] + b1) * sc;
            float v2 = (acc[fm][fn][2] + b0) * sc;
            float v3 = (acc[fm][fn][3] + b1) * sc;
            if (TOF32) {
                *(float2*)&Cf[(size_t)row * ldc + col]       = make_float2(v0, v1);
                *(float2*)&Cf[(size_t)(row + 8) * ldc + col] = make_float2(v2, v3);
            } else {
                store_splith(Chi, Clo, (size_t)row * ldc + col,       v0, v1);
                store_splith(Chi, Clo, (size_t)(row + 8) * ldc + col, v2, v3);
            }
        }
    }
}

// ---------------------------------------------------------------------------
// Flash attention on mma.sync, split-fp16 x2 (Br=Bc=64, 128 thr).
// Q exact (hi+lo), K/V single fp16. Descending-qb order; exp2-domain softmax.
// ---------------------------------------------------------------------------
#define AST 72        // b16 row stride (144B: 16B-aligned, ldmatrix conflict-free)
#define QHI_O 0u
#define QLO_O 9216u
#define KH_O  18432u
#define VH_O  27648u
#define ATTN_SMEM 36864

__global__ __launch_bounds__(128) void attn_mma()
{
    extern __shared__ char smc[];
    const uint32_t sb = smem_u32(smc);
    const int tid = threadIdx.x, lane = tid & 31, w = tid >> 5;
    const int g = lane >> 2, tg = lane & 3;
    const int qb = (int)gridDim.x - 1 - (int)blockIdx.x;   // heavy blocks first
    const int h = blockIdx.y, b = blockIdx.z;
    const int qbase = qb * 64;
    const size_t rowb = (size_t)b * SEQ;
    const int hoff = h * HD;

    // load Q tile (hi/lo), 64 rows x 64 fp16
    #pragma unroll
    for (int i = 0; i < 4; i++) {
        int slot = tid + 128 * i;
        int r = slot >> 3, q8 = slot & 7;
        size_t go = (rowb + qbase + r) * 3072 + hoff + q8 * 8;
        uint32_t so = (uint32_t)(r * AST + q8 * 8) * 2u;
        *(uint4*)(smc + QHI_O + so) = *(const uint4*)(g_QKVhi + go);
        *(uint4*)(smc + QLO_O + so) = *(const uint4*)(g_QKVlo + go);
    }

    float o[8][4];
    #pragma unroll
    for (int fn = 0; fn < 8; fn++)
        #pragma unroll
        for (int c = 0; c < 4; c++) o[fn][c] = 0.f;
    float m0 = -1e30f, m1 = -1e30f, l0 = 0.f, l1 = 0.f;

    for (int kb = 0; kb <= qb; kb++) {
        __syncthreads();   // Q visible (first) / prev compute done (later)
        const int kbase = kb * 64;
        #pragma unroll
        for (int i = 0; i < 4; i++) {
            int slot = tid + 128 * i;
            int r = slot >> 3, q8 = slot & 7;
            size_t go = (rowb + kbase + r) * 3072 + hoff + q8 * 8;
            uint32_t so = (uint32_t)(r * AST + q8 * 8) * 2u;
            *(uint4*)(smc + KH_O + so) = *(const uint4*)(g_QKVhi + go + 1024);
            *(uint4*)(smc + VH_O + so) = *(const uint4*)(g_QKVhi + go + 2048);
        }
        __syncthreads();

        // ---- S = Q @ K^T (log2 units: Q pre-scaled) ----
        float s[8][4];
        #pragma unroll
        for (int fn = 0; fn < 8; fn++)
            #pragma unroll
            for (int c = 0; c < 4; c++) s[fn][c] = 0.f;

        #pragma unroll
        for (int kk = 0; kk < 64; kk += 16) {
            uint32_t qh[4], ql[4];
            uint32_t ra = sb + (uint32_t)((w * 16 + (lane & 7)
                          + 8 * ((lane >> 3) & 1)) * AST
                          + kk + 8 * (lane >> 4)) * 2u;
            ldm_x4(qh, ra + QHI_O);
            ldm_x4(ql, ra + QLO_O);
            #pragma unroll
            for (int i = 0; i < 4; i++) {
                uint32_t rb = sb + (uint32_t)((i * 16 + (lane & 7)
                              + 8 * (lane >> 4)) * AST
                              + kk + 8 * ((lane >> 3) & 1)) * 2u;
                uint32_t th[4];
                ldm_x4(th, rb + KH_O);
                mma_f16(s[2*i],   qh, th);
                mma_f16(s[2*i],   ql, th);
                mma_f16(s[2*i+1], qh, th + 2);
                mma_f16(s[2*i+1], ql, th + 2);
            }
        }

        // ---- causal mask on diagonal tile ----
        if (kb == qb) {
            const int lr0 = w * 16 + g, lr1 = lr0 + 8;
            #pragma unroll
            for (int fn = 0; fn < 8; fn++) {
                int c0 = fn * 8 + 2 * tg;
                if (c0     > lr0) s[fn][0] = -1e30f;
                if (c0 + 1 > lr0) s[fn][1] = -1e30f;
                if (c0     > lr1) s[fn][2] = -1e30f;
                if (c0 + 1 > lr1) s[fn][3] = -1e30f;
            }
        }

        // ---- online softmax (exp2 domain) ----
        float rm0 = -1e30f, rm1 = -1e30f;
        #pragma unroll
        for (int fn = 0; fn < 8; fn++) {
            rm0 = fmaxf(rm0, fmaxf(s[fn][0], s[fn][1]));
            rm1 = fmaxf(rm1, fmaxf(s[fn][2], s[fn][3]));
        }
        rm0 = fmaxf(rm0, __shfl_xor_sync(0xffffffffu, rm0, 1));
        rm0 = fmaxf(rm0, __shfl_xor_sync(0xffffffffu, rm0, 2));
        rm1 = fmaxf(rm1, __shfl_xor_sync(0xffffffffu, rm1, 1));
        rm1 = fmaxf(rm1, __shfl_xor_sync(0xffffffffu, rm1, 2));
        const float mn0 = fmaxf(m0, rm0), mn1 = fmaxf(m1, rm1);
        const float c0 = ex2f(m0 - mn0), c1 = ex2f(m1 - mn1);
        m0 = mn0; m1 = mn1;
        float sum0 = 0.f, sum1 = 0.f;
        #pragma unroll
        for (int fn = 0; fn < 8; fn++) {
            s[fn][0] = ex2f(s[fn][0] - mn0); sum0 += s[fn][0];
            s[fn][1] = ex2f(s[fn][1] - mn0); sum0 += s[fn][1];
            s[fn][2] = ex2f(s[fn][2] - mn1); sum1 += s[fn][2];
            s[fn][3] = ex2f(s[fn][3] - mn1); sum1 += s[fn][3];
        }
        sum0 += __shfl_xor_sync(0xffffffffu, sum0, 1);
        sum0 += __shfl_xor_sync(0xffffffffu, sum0, 2);
        sum1 += __shfl_xor_sync(0xffffffffu, sum1, 1);
        sum1 += __shfl_xor_sync(0xffffffffu, sum1, 2);
        l0 = l0 * c0 + sum0;
        l1 = l1 * c1 + sum1;
        #pragma unroll
        for (int fn = 0; fn < 8; fn++) {
            o[fn][0] *= c0; o[fn][1] *= c0;
            o[fn][2] *= c1; o[fn][3] *= c1;
        }

        // ---- O += P @ V  (P split hi/lo fp16; V single, ldmatrix.trans) ----
        #pragma unroll
        for (int kk = 0; kk < 64; kk += 16) {
            const int f0 = kk >> 3, f1 = f0 + 1;
            uint32_t ph[4], pl[4];
            split2h(s[f0][0], s[f0][1], ph[0], pl[0]);
            split2h(s[f0][2], s[f0][3], ph[1], pl[1]);
            split2h(s[f1][0], s[f1][1], ph[2], pl[2]);
            split2h(s[f1][2], s[f1][3], ph[3], pl[3]);
            uint32_t rv = sb + (uint32_t)((kk + (lane & 15)) * AST) * 2u;
            #pragma unroll
            for (int fn = 0; fn < 8; fn++) {
                uint32_t vh[2];
                ldm_x2t(vh, rv + VH_O + (uint32_t)(fn * 16));
                mma_f16(o[fn], ph, vh);
                mma_f16(o[fn], pl, vh);
            }
        }
    }

    // ---- epilogue: normalize, split-store AO ----
    const float i0 = 1.f / l0, i1 = 1.f / l1;
    const size_t r0 = rowb + qbase + w * 16 + g;
    #pragma unroll
    for (int fn = 0; fn < 8; fn++) {
        int col = hoff + fn * 8 + 2 * tg;
        store_splith(g_AOhi, g_AOlo, r0 * DM + col,       o[fn][0] * i0, o[fn][1] * i0);
        store_splith(g_AOhi, g_AOlo, (r0 + 8) * DM + col, o[fn][2] * i1, o[fn][3] * i1);
    }
}

// ---------------------------------------------------------------------------
// Launch
// ---------------------------------------------------------------------------
extern "C" void kernel_launch(void* const* d_in, const int* in_sizes, int n_in,
                              void* d_out, int out_size)
{
    const float* X  = (const float*)d_in[0];
    const float* Wq = (const float*)d_in[1];
    const float* bq = (const float*)d_in[2];
    const float* Wk = (const float*)d_in[3];
    const float* bk = (const float*)d_in[4];
    const float* Wv = (const float*)d_in[5];
    const float* bv = (const float*)d_in[6];
    const float* Wo = (const float*)d_in[7];
    const float* bo = (const float*)d_in[8];
    float* out = (float*)d_out;

    __half *Xhi, *Xlo, *WT, *QKVhi, *QKVlo, *AOhi, *AOlo;
    float* biasP;
    cudaGetSymbolAddress((void**)&Xhi,   g_Xhi);
    cudaGetSymbolAddress((void**)&Xlo,   g_Xlo);
    cudaGetSymbolAddress((void**)&WT,    g_WT);
    cudaGetSymbolAddress((void**)&QKVhi, g_QKVhi);
    cudaGetSymbolAddress((void**)&QKVlo, g_QKVlo);
    cudaGetSymbolAddress((void**)&AOhi,  g_AOhi);
    cudaGetSymbolAddress((void**)&AOlo,  g_AOlo);
    cudaGetSymbolAddress((void**)&biasP, g_bias);

    cudaFuncSetAttribute(gemm_mma<false>,
        cudaFuncAttributeMaxDynamicSharedMemorySize, (int)GEMM_SMEM);
    cudaFuncSetAttribute(gemm_mma<true>,
        cudaFuncAttributeMaxDynamicSharedMemorySize, (int)GEMM_SMEM);
    cudaFuncSetAttribute(attn_mma,
        cudaFuncAttributeMaxDynamicSharedMemorySize, (int)ATTN_SMEM);

    const int n4 = MR * DM / 4;

    split_f32h<<<(n4 + 255) / 256, 256>>>(X, Xhi, Xlo, n4);
    split_wT4<<<dim3(DM / 32, DM / 32, 4), dim3(32, 8)>>>(Wq, Wk, Wv, Wo, WT);
    concat_bias<<<16, 256>>>(bq, bk, bv, bo, biasP);

    // fused QKV projection (N=3072), Q region scaled by log2e/8, split-fp16 out
    gemm_mma<false><<<dim3(24, 32), 256, GEMM_SMEM>>>(
        Xhi, Xlo, WT, biasP, nullptr, QKVhi, QKVlo, 3072, 1);

    // causal attention (Br=Bc=64), split-fp16 out
    attn_mma<<<dim3(SEQ / 64, NH, BATCH), 128, ATTN_SMEM>>>();

    // output projection, fp32 out
    const size_t WSZ = (size_t)DM * DM;
    gemm_mma<true><<<dim3(8, 32), 256, GEMM_SMEM>>>(
        AOhi, AOlo, WT + 3 * WSZ, biasP + 3072,
        out, nullptr, nullptr, 1024, 0);
}